// round 11
// baseline (speedup 1.0000x reference)
#include <cuda_runtime.h>
#include <cuda_bf16.h>
#include <cstdint>

#define NN 100000
#define NE 400000
#define INF 128
#define HIDF 1024
#define OUTF 64
#define SCAN_B 1024
#define NBLK ((NN + SCAN_B - 1) / SCAN_B)

// ---------------- scratch (device globals; no allocation allowed) ----------------
__device__ float g_deg[NN];
__device__ float g_dinv[NN];
__device__ int g_cnt[NN];
__device__ int g_inc[NN];
__device__ int g_bsum[NBLK];
__device__ int g_offs[NN];
__device__ int g_fill[NN];
__device__ int g_csr_src[NE];
__device__ float g_csr_nrm[NE];
__device__ __align__(256) float g_y[(size_t)NN * INF];
__device__ __align__(256) float g_z[(size_t)NN * OUTF];
__device__ __align__(256) float g_w1t[(size_t)HIDF * INF];   // [hid][in] tf32
__device__ __align__(256) float g_w2t[(size_t)OUTF * HIDF];  // [out][hid] tf32

// ---------------- helpers ----------------
__device__ __forceinline__ uint32_t f2tf32(float x) {
    uint32_t r;
    asm("cvt.rna.tf32.f32 %0, %1;" : "=r"(r) : "f"(x));
    return r;
}
__device__ __forceinline__ void mma16n8k8(float* c, const uint32_t* a, const uint32_t* b) {
    asm volatile(
        "mma.sync.aligned.m16n8k8.row.col.f32.tf32.tf32.f32 "
        "{%0,%1,%2,%3}, {%4,%5,%6,%7}, {%8,%9}, {%0,%1,%2,%3};"
        : "+f"(c[0]), "+f"(c[1]), "+f"(c[2]), "+f"(c[3])
        : "r"(a[0]), "r"(a[1]), "r"(a[2]), "r"(a[3]), "r"(b[0]), "r"(b[1]));
}
__device__ __forceinline__ void ldsm_x4(uint32_t* r, uint32_t addr) {
    asm volatile("ldmatrix.sync.aligned.m8n8.x4.shared.b16 {%0,%1,%2,%3}, [%4];"
                 : "=r"(r[0]), "=r"(r[1]), "=r"(r[2]), "=r"(r[3]) : "r"(addr));
}
__device__ __forceinline__ uint32_t smem_u32(const void* p) {
    uint32_t a;
    asm("{ .reg .u64 t; cvta.to.shared.u64 t, %1; cvt.u32.u64 %0, t; }" : "=r"(a) : "l"(p));
    return a;
}
#define CP_ASYNC16(dst, src) \
    asm volatile("cp.async.cg.shared.global [%0], [%1], 16;" :: "r"(dst), "l"(src))
#define CP_COMMIT() asm volatile("cp.async.commit_group;" ::: "memory")
#define CP_WAIT0() asm volatile("cp.async.wait_group 0;" ::: "memory")

// ---------------- graph prep ----------------
__global__ void init_kernel(float* __restrict__ deg, int* __restrict__ cnt,
                            int* __restrict__ fill, int n) {
    int i = blockIdx.x * blockDim.x + threadIdx.x;
    if (i < n) { deg[i] = 1.0f; cnt[i] = 0; fill[i] = 0; }
}
__global__ void accum_kernel(const int* __restrict__ ei, const float* __restrict__ ew,
                             float* __restrict__ deg, int* __restrict__ cnt, int E) {
    int e = blockIdx.x * blockDim.x + threadIdx.x;
    if (e < E) {
        int d = ei[E + e];
        atomicAdd(&deg[d], ew[e]);
        atomicAdd(&cnt[d], 1);
    }
}
__global__ void dinv_kernel(const float* __restrict__ deg, float* __restrict__ dinv, int n) {
    int i = blockIdx.x * blockDim.x + threadIdx.x;
    if (i < n) {
        float d = deg[i];
        dinv[i] = d > 0.0f ? rsqrtf(d) : 0.0f;
    }
}
__global__ void scan_block_kernel(const int* __restrict__ cnt, int* __restrict__ inc,
                                  int* __restrict__ bsum, int n) {
    __shared__ int s[SCAN_B];
    int i = blockIdx.x * SCAN_B + threadIdx.x;
    int v = (i < n) ? cnt[i] : 0;
    s[threadIdx.x] = v;
    __syncthreads();
    for (int d = 1; d < SCAN_B; d <<= 1) {
        int t = (threadIdx.x >= d) ? s[threadIdx.x - d] : 0;
        __syncthreads();
        s[threadIdx.x] += t;
        __syncthreads();
    }
    if (i < n) inc[i] = s[threadIdx.x];
    if (threadIdx.x == SCAN_B - 1) bsum[blockIdx.x] = s[SCAN_B - 1];
}
__global__ void scan_bsum_kernel(int* __restrict__ bsum, int nb) {
    if (threadIdx.x == 0 && blockIdx.x == 0) {
        int acc = 0;
        for (int b = 0; b < nb; b++) { int t = bsum[b]; bsum[b] = acc; acc += t; }
    }
}
__global__ void scan_final_kernel(const int* __restrict__ cnt, const int* __restrict__ inc,
                                  const int* __restrict__ bsum, int* __restrict__ offs, int n) {
    int i = blockIdx.x * SCAN_B + threadIdx.x;
    if (i < n) offs[i] = bsum[blockIdx.x] + inc[i] - cnt[i];
}
__global__ void fill_csr_kernel(const int* __restrict__ ei, const float* __restrict__ ew,
                                const float* __restrict__ dinv, const int* __restrict__ offs,
                                int* __restrict__ fill, int* __restrict__ csr_src,
                                float* __restrict__ csr_nrm, int E) {
    int e = blockIdx.x * blockDim.x + threadIdx.x;
    if (e >= E) return;
    int s = ei[e], d = ei[E + e];
    int pos = offs[d] + atomicAdd(&fill[d], 1);
    csr_src[pos] = s;
    csr_nrm[pos] = dinv[s] * ew[e] * dinv[d];
}

// one warp per dst node
template <int F, bool BIAS>
__global__ void gather_kernel(const int* __restrict__ csr_src, const float* __restrict__ csr_nrm,
                              const int* __restrict__ offs, const int* __restrict__ cnt,
                              const float* __restrict__ dinv, const float* __restrict__ feat,
                              const float* __restrict__ bias, float* __restrict__ out) {
    int warp = (blockIdx.x * blockDim.x + threadIdx.x) >> 5;
    int lane = threadIdx.x & 31;
    if (warp >= NN) return;
    int beg = offs[warp], n = cnt[warp];
    float si = dinv[warp];
    si = si * si;
    if (F == 128) {
        float4 v = reinterpret_cast<const float4*>(feat + (size_t)warp * 128)[lane];
        float4 acc;
        acc.x = si * v.x; acc.y = si * v.y; acc.z = si * v.z; acc.w = si * v.w;
        for (int j = beg; j < beg + n; j++) {
            int s = csr_src[j];
            float nrm = csr_nrm[j];
            float4 f = reinterpret_cast<const float4*>(feat + (size_t)s * 128)[lane];
            acc.x += nrm * f.x; acc.y += nrm * f.y; acc.z += nrm * f.z; acc.w += nrm * f.w;
        }
        reinterpret_cast<float4*>(out + (size_t)warp * 128)[lane] = acc;
    } else {
        float2 v = reinterpret_cast<const float2*>(feat + (size_t)warp * 64)[lane];
        float2 acc;
        acc.x = si * v.x; acc.y = si * v.y;
        for (int j = beg; j < beg + n; j++) {
            int s = csr_src[j];
            float nrm = csr_nrm[j];
            float2 f = reinterpret_cast<const float2*>(feat + (size_t)s * 64)[lane];
            acc.x += nrm * f.x; acc.y += nrm * f.y;
        }
        if (BIAS) {
            float2 b = reinterpret_cast<const float2*>(bias)[lane];
            acc.x += b.x; acc.y += b.y;
        }
        reinterpret_cast<float2*>(out + (size_t)warp * 64)[lane] = acc;
    }
}

// W[K,N] -> Wt[N,K], tf32-rounded
__global__ void wtrans_kernel(const float* __restrict__ W, float* __restrict__ Wt, int K, int N) {
    int idx = blockIdx.x * blockDim.x + threadIdx.x;
    if (idx >= K * N) return;
    int k = idx / N, n = idx - k * N;
    Wt[(size_t)n * K + k] = __uint_as_float(f2tf32(W[idx]));
}

// ---------------- fused 2-layer GEMM (512 thr, 16 warps 4x4) ----------------
#define AS_STR 132
#define HS_STR 68
#define OFF_AS 0
#define OFF_BS (128 * AS_STR)                       // 2 buffers of [64][132]
#define OFF_HS (OFF_BS + 2 * 64 * AS_STR)
#define OFF_W2 (OFF_HS + 128 * HS_STR)              // 2 buffers of [64][68]
#define FUSED_SMEM ((OFF_W2 + 2 * 64 * HS_STR) * 4)
#define BS_BYTES (64 * AS_STR * 4)
#define W2_BYTES (64 * HS_STR * 4)
#define FTHREADS 512

__global__ void __launch_bounds__(FTHREADS) fused_gemm_kernel(
    const float* __restrict__ Y, const float* __restrict__ W1t,
    const float* __restrict__ b1, const float* __restrict__ W2t,
    float* __restrict__ Z, int M) {
    extern __shared__ uint32_t sm[];
    uint32_t* As = sm + OFF_AS;
    uint32_t* Hs = sm + OFF_HS;

    int tid = threadIdx.x, lane = tid & 31, wid = tid >> 5;
    int wm = wid & 3, wn = wid >> 2;   // 4 m-warps x 4 n-warps
    int m0 = blockIdx.x * 128;

    uint32_t as_u = smem_u32(sm + OFF_AS);
    uint32_t bs_u = smem_u32(sm + OFF_BS);
    uint32_t hs_u = smem_u32(sm + OFF_HS);
    uint32_t w2_u = smem_u32(sm + OFF_W2);

    // ldmatrix lane mapping (x4)
    int lrow = (((lane >> 3) & 1) << 3) + (lane & 7);
    int lcol = (lane >> 4) << 2;
    int ar = lane >> 2, ac = lane & 3;  // mma fragment coords

    // ---- stage Y tile (tf32): 4096 16B-units / 512 threads = 8 iters ----
#pragma unroll
    for (int i = 0; i < 8; i++) {
        int u = tid + i * FTHREADS;
        int r = u >> 5, c = (u & 31) * 4;
        float4 v;
        if (m0 + r < M)
            v = *reinterpret_cast<const float4*>(Y + (size_t)(m0 + r) * INF + c);
        else
            v = make_float4(0.f, 0.f, 0.f, 0.f);
        uint32_t* p = As + r * AS_STR + c;
        p[0] = f2tf32(v.x); p[1] = f2tf32(v.y); p[2] = f2tf32(v.z); p[3] = f2tf32(v.w);
    }

    // ---- cp.async chunk loader ----
    auto load_chunk = [&](int ch, int buf) {
        int c0 = ch * 64;
        uint32_t bdst = bs_u + buf * BS_BYTES;
#pragma unroll
        for (int i = 0; i < 4; i++) {
            int u = tid + i * FTHREADS;     // 0..2047 16B units of W1 chunk
            int r = u >> 5, c = (u & 31) * 4;
            CP_ASYNC16(bdst + (r * AS_STR + c) * 4,
                       W1t + (size_t)(c0 + r) * INF + c);
        }
        uint32_t wdst = w2_u + buf * W2_BYTES;
#pragma unroll
        for (int i = 0; i < 2; i++) {
            int u = tid + i * FTHREADS;     // 0..1023 16B units of W2 chunk
            int r = u >> 4, c = (u & 15) * 4;
            CP_ASYNC16(wdst + (r * HS_STR + c) * 4,
                       W2t + (size_t)r * HIDF + c0 + c);
        }
        CP_COMMIT();
    };

    load_chunk(0, 0);

    float acc_out[2][2][4];
#pragma unroll
    for (int mt = 0; mt < 2; mt++)
#pragma unroll
        for (int nt = 0; nt < 2; nt++)
#pragma unroll
            for (int i = 0; i < 4; i++) acc_out[mt][nt][i] = 0.0f;

    for (int ch = 0; ch < HIDF / 64; ch++) {
        int buf = ch & 1;
        CP_WAIT0();
        __syncthreads();
        if (ch + 1 < HIDF / 64) load_chunk(ch + 1, buf ^ 1);

        uint32_t bsb = bs_u + buf * BS_BYTES;
        uint32_t w2b = w2_u + buf * W2_BYTES;

        // ---- mma1: h_chunk[128x64] = y_tile @ W1chunk^T, K=128 ----
        float acc_h[2][2][4];
#pragma unroll
        for (int mt = 0; mt < 2; mt++)
#pragma unroll
            for (int nt = 0; nt < 2; nt++)
#pragma unroll
                for (int i = 0; i < 4; i++) acc_h[mt][nt][i] = 0.0f;
#pragma unroll
        for (int kk = 0; kk < 128; kk += 8) {
            uint32_t a[2][4], bp[4];
#pragma unroll
            for (int mt = 0; mt < 2; mt++) {
                int rb = wm * 32 + mt * 16;
                ldsm_x4(a[mt], as_u + ((rb + lrow) * AS_STR + kk + lcol) * 4);
            }
            ldsm_x4(bp, bsb + ((wn * 16 + lrow) * AS_STR + kk + lcol) * 4);
            uint32_t b0[2] = {bp[0], bp[2]};   // n rows wn*16..+8
            uint32_t b1r[2] = {bp[1], bp[3]};  // n rows wn*16+8..+16
#pragma unroll
            for (int mt = 0; mt < 2; mt++) {
                mma16n8k8(acc_h[mt][0], a[mt], b0);
                mma16n8k8(acc_h[mt][1], a[mt], b1r);
            }
        }
        // bias + relu -> Hs (tf32)
        int c0 = ch * 64;
#pragma unroll
        for (int mt = 0; mt < 2; mt++) {
#pragma unroll
            for (int half = 0; half < 2; half++) {
                int row = wm * 32 + mt * 16 + ar + half * 8;
#pragma unroll
                for (int nt = 0; nt < 2; nt++) {
                    int col = wn * 16 + nt * 8 + 2 * ac;
                    float bv0 = __ldg(b1 + c0 + col);
                    float bv1 = __ldg(b1 + c0 + col + 1);
                    float v0 = fmaxf(acc_h[mt][nt][half * 2 + 0] + bv0, 0.0f);
                    float v1 = fmaxf(acc_h[mt][nt][half * 2 + 1] + bv1, 0.0f);
                    uint32_t* p = Hs + row * HS_STR + col;
                    p[0] = f2tf32(v0);
                    p[1] = f2tf32(v1);
                }
            }
        }
        __syncthreads();

        // ---- mma2: acc_out += h_chunk @ W2chunk^T, K=64 ----
#pragma unroll
        for (int kk = 0; kk < 64; kk += 8) {
            uint32_t a[2][4], bp[4];
#pragma unroll
            for (int mt = 0; mt < 2; mt++) {
                int rb = wm * 32 + mt * 16;
                ldsm_x4(a[mt], hs_u + ((rb + lrow) * HS_STR + kk + lcol) * 4);
            }
            ldsm_x4(bp, w2b + ((wn * 16 + lrow) * HS_STR + kk + lcol) * 4);
            uint32_t b0[2] = {bp[0], bp[2]};
            uint32_t b1r[2] = {bp[1], bp[3]};
#pragma unroll
            for (int mt = 0; mt < 2; mt++) {
                mma16n8k8(acc_out[mt][0], a[mt], b0);
                mma16n8k8(acc_out[mt][1], a[mt], b1r);
            }
        }
    }

    // ---- epilogue: Z tile [128 x 64] ----
#pragma unroll
    for (int mt = 0; mt < 2; mt++) {
#pragma unroll
        for (int half = 0; half < 2; half++) {
            int row = m0 + wm * 32 + mt * 16 + ar + half * 8;
            if (row >= M) continue;
#pragma unroll
            for (int nt = 0; nt < 2; nt++) {
                int col = wn * 16 + nt * 8 + 2 * ac;
                *reinterpret_cast<float2*>(Z + (size_t)row * OUTF + col) =
                    make_float2(acc_out[mt][nt][half * 2 + 0], acc_out[mt][nt][half * 2 + 1]);
            }
        }
    }
}

// ---------------- launch ----------------
extern "C" void kernel_launch(void* const* d_in, const int* in_sizes, int n_in,
                              void* d_out, int out_size) {
    const float* x = (const float*)d_in[0];
    const int* ei = (const int*)d_in[1];
    const float* ew = (const float*)d_in[2];
    const float* W1 = (const float*)d_in[3];
    const float* b1 = (const float*)d_in[4];
    const float* W2 = (const float*)d_in[5];
    const float* b2 = (const float*)d_in[6];
    float* out = (float*)d_out;

    float *deg, *dinv, *y, *z, *w1t, *w2t, *csr_nrm;
    int *cnt, *inc, *bsum, *offs, *fill, *csr_src;
    cudaGetSymbolAddress((void**)&deg, g_deg);
    cudaGetSymbolAddress((void**)&dinv, g_dinv);
    cudaGetSymbolAddress((void**)&y, g_y);
    cudaGetSymbolAddress((void**)&z, g_z);
    cudaGetSymbolAddress((void**)&w1t, g_w1t);
    cudaGetSymbolAddress((void**)&w2t, g_w2t);
    cudaGetSymbolAddress((void**)&cnt, g_cnt);
    cudaGetSymbolAddress((void**)&inc, g_inc);
    cudaGetSymbolAddress((void**)&bsum, g_bsum);
    cudaGetSymbolAddress((void**)&offs, g_offs);
    cudaGetSymbolAddress((void**)&fill, g_fill);
    cudaGetSymbolAddress((void**)&csr_src, g_csr_src);
    cudaGetSymbolAddress((void**)&csr_nrm, g_csr_nrm);

    static bool attr_set = false;
    if (!attr_set) {
        cudaFuncSetAttribute(fused_gemm_kernel,
                             cudaFuncAttributeMaxDynamicSharedMemorySize, FUSED_SMEM);
        attr_set = true;
    }

    // 1) degrees + counts + norm
    init_kernel<<<(NN + 255) / 256, 256>>>(deg, cnt, fill, NN);
    accum_kernel<<<(NE + 255) / 256, 256>>>(ei, ew, deg, cnt, NE);
    dinv_kernel<<<(NN + 255) / 256, 256>>>(deg, dinv, NN);

    // 2) CSR build
    scan_block_kernel<<<NBLK, SCAN_B>>>(cnt, inc, bsum, NN);
    scan_bsum_kernel<<<1, 32>>>(bsum, NBLK);
    scan_final_kernel<<<NBLK, SCAN_B>>>(cnt, inc, bsum, offs, NN);
    fill_csr_kernel<<<(NE + 255) / 256, 256>>>(ei, ew, dinv, offs, fill, csr_src, csr_nrm, NE);

    // 3) weights: transpose + tf32 round
    wtrans_kernel<<<(INF * HIDF + 255) / 256, 256>>>(W1, w1t, INF, HIDF);
    wtrans_kernel<<<(HIDF * OUTF + 255) / 256, 256>>>(W2, w2t, HIDF, OUTF);

    // 4) y = Â x
    gather_kernel<128, false><<<(NN * 32 + 255) / 256, 256>>>(csr_src, csr_nrm, offs, cnt,
                                                              dinv, x, nullptr, y);
    // 5) z = relu(y@W1+b1)@W2  (fused; h stays in SMEM)
    fused_gemm_kernel<<<(NN + 127) / 128, FTHREADS, FUSED_SMEM>>>(y, w1t, b1, w2t, z, NN);

    // 6) out = Â z + b2
    gather_kernel<64, true><<<(NN * 32 + 255) / 256, 256>>>(csr_src, csr_nrm, offs, cnt,
                                                            dinv, z, b2, out);
}